// round 13
// baseline (speedup 1.0000x reference)
#include <cuda_runtime.h>
#include <cuda_fp16.h>
#include <math.h>
#include <stdint.h>

// Problem constants
#define NB        8
#define CD        64
#define HH        4096
#define NPTS      (NB*HH)    // 32768
#define NCODE     8192
#define ZQ_ELEMS  (NB*CD*HH) // 2097152

// Output layout (flat float32): [z_q | loss | indices | perplexity]
#define OUT_ZQ    0
#define OUT_LOSS  ZQ_ELEMS
#define OUT_IDX   (ZQ_ELEMS + 1)
#define OUT_PERP  (ZQ_ELEMS + 1 + NPTS)

#define DELTA     5e-5f      // prune window; >= 2x rigorous 1-pass fp16 error bound

// B fragments (hi fp16 only) for mma.m16n8k16: [nf(1024)][kc(4)][lane(32)]
__device__ uint2  g_BfragH[1024 * 4 * 32];  // 1 MB
__device__ float  g_Et[CD * NCODE];         // transposed fp32 codebook [k][n], 2 MB
__device__ float  g_enorm[NCODE];
__device__ float  g_nzn[NPTS];              // -|z|^2 per row (exact chain)
__device__ float  g_cval[NPTS * 8];         // top-2 approx values x 4 lanes
__device__ int    g_cidx[NPTS * 8];
__device__ int    g_rflag[NPTS];            // fallback flag
__device__ int    g_idx[NPTS];
__device__ int    g_hist[NCODE];
__device__ float  g_partial[2048];

// ---------------------------------------------------------------------------
__device__ __forceinline__ uint32_t pack_h2(__half a, __half b) {
    __half2 h = __halves2half2(a, b);
    return *(uint32_t*)&h;
}

__device__ __forceinline__ void mma_f16(float& d0, float& d1, float& d2, float& d3,
                                        uint32_t a0, uint32_t a1, uint32_t a2, uint32_t a3,
                                        uint32_t b0, uint32_t b1) {
    asm volatile(
        "mma.sync.aligned.m16n8k16.row.col.f32.f16.f16.f32 "
        "{%0,%1,%2,%3},{%4,%5,%6,%7},{%8,%9},{%0,%1,%2,%3};"
        : "+f"(d0), "+f"(d1), "+f"(d2), "+f"(d3)
        : "r"(a0), "r"(a1), "r"(a2), "r"(a3), "r"(b0), "r"(b1));
}

__device__ __forceinline__ void cp_async16(uint32_t saddr, const void* gptr) {
    asm volatile("cp.async.cg.shared.global [%0], [%1], 16;" :: "r"(saddr), "l"(gptr));
}

// Branchy top-3 tracker on NAMED scalars (outer branch rarely taken).
#define TOP3(U, IX, B0V, B0I, B1V, B1I, B2V) do {                             \
    float _u = (U);                                                           \
    if (_u > B2V) {                                                           \
        if (_u > B0V)      { B2V = B1V; B1V = B0V; B1I = B0I; B0V = _u; B0I = (IX); } \
        else if (_u > B1V) { B2V = B1V; B1V = _u; B1I = (IX); }               \
        else               { B2V = _u; }                                      \
    }                                                                         \
} while (0)

// ---------------------------------------------------------------------------
// Prep A: transpose E -> g_Et, |e|^2 (reference chain), zero histogram.
// grid 2048 x 256.
// ---------------------------------------------------------------------------
__global__ void vq_prep(const float* __restrict__ E) {
    int idx = blockIdx.x * 256 + threadIdx.x;
    if (idx < CD * NCODE) {
        int d = idx >> 13;
        int n = idx & (NCODE - 1);
        g_Et[idx] = E[n * CD + d];
    }
    if (idx < NCODE) {
        const float* r = E + idx * CD;
        float s = 0.f;
#pragma unroll
        for (int d = 0; d < CD; d++) s = __fadd_rn(s, __fmul_rn(r[d], r[d]));
        g_enorm[idx] = s;
        g_hist[idx] = 0;
    }
}

// ---------------------------------------------------------------------------
// Prep B: pack codebook hi-fp16 fragments of 2E. grid 512 x 256.
// ---------------------------------------------------------------------------
__global__ void vq_prep_bfrag(const float* __restrict__ E) {
    int idx = blockIdx.x * 256 + threadIdx.x;     // [nf*4+kc]*32 + lane
    int lane = idx & 31;
    int kc = (idx >> 5) & 3;
    int nf = idx >> 7;
    int n = nf * 8 + (lane >> 2);
    int k0 = kc * 16 + (lane & 3) * 2;
    const float* r = E + n * CD;
    __half h0 = __float2half_rn(2.0f * r[k0]);
    __half h1 = __float2half_rn(2.0f * r[k0 + 1]);
    __half h2 = __float2half_rn(2.0f * r[k0 + 8]);
    __half h3 = __float2half_rn(2.0f * r[k0 + 9]);
    uint2 v;
    v.x = pack_h2(h0, h1);
    v.y = pack_h2(h2, h3);
    g_BfragH[idx] = v;
}

// ---------------------------------------------------------------------------
// Phase 1: single-pass fp16 approx GEMM + top-3 tracking (named scalars).
// grid 128 x 256.
// ---------------------------------------------------------------------------
__global__ void __launch_bounds__(256, 1) vq_scan(const float* __restrict__ z) {
    __shared__ uint2 Bs[2][512];     // 8 KB double buffer (n-tile of 32 codes)

    const int tid = threadIdx.x;
    const int lane = tid & 31;
    const int w = tid >> 5;
    const int blk = blockIdx.x;
    const int b = (blk * 256) >> 12;
    const int hb = (blk * 256) & (HH - 1);
    const float* zb = z + b * (CD * HH);
    const int hw = hb + w * 32;
    const int Wrow = blk * 256 + w * 32;

    // exact -|z|^2 per row (reference sequential chain)
    {
        float s = 0.f;
        int h = hw + lane;
#pragma unroll
        for (int k = 0; k < CD; k++) {
            float v = zb[k * HH + h];
            s = __fadd_rn(s, __fmul_rn(v, v));
        }
        g_nzn[Wrow + lane] = -s;
    }

    // A fragments (hi fp16), resident for whole N sweep
    uint32_t Ahi[2][4][4];
#pragma unroll
    for (int mf = 0; mf < 2; mf++) {
        int r0 = hw + mf * 16 + (lane >> 2);
        int r1 = r0 + 8;
#pragma unroll
        for (int kc = 0; kc < 4; kc++) {
            int k0 = kc * 16 + (lane & 3) * 2;
#pragma unroll
            for (int q = 0; q < 4; q++) {
                int rr = (q & 1) ? r1 : r0;
                int kk = k0 + ((q & 2) ? 8 : 0);
                __half hA = __float2half_rn(zb[kk * HH + rr]);
                __half hB = __float2half_rn(zb[(kk + 1) * HH + rr]);
                Ahi[mf][kc][q] = pack_h2(hA, hB);
            }
        }
    }

    // per-slot trackers (slot = mf,rr), all named scalars
    float b0v00 = -3.4e38f, b1v00 = -3.4e38f, b2v00 = -3.4e38f;
    float b0v01 = -3.4e38f, b1v01 = -3.4e38f, b2v01 = -3.4e38f;
    float b0v10 = -3.4e38f, b1v10 = -3.4e38f, b2v10 = -3.4e38f;
    float b0v11 = -3.4e38f, b1v11 = -3.4e38f, b2v11 = -3.4e38f;
    int b0i00 = 0, b1i00 = 0;
    int b0i01 = 0, b1i01 = 0;
    int b0i10 = 0, b1i10 = 0;
    int b0i11 = 0, b1i11 = 0;

    const int NT = NCODE / 32;   // 256 n-tiles

    {
        uint32_t sa = (uint32_t)__cvta_generic_to_shared(&Bs[0][tid * 2]);
        cp_async16(sa, &g_BfragH[tid * 2]);
        asm volatile("cp.async.commit_group;" ::: "memory");
    }

#pragma unroll 1
    for (int t = 0; t < NT; t++) {
        const int cur = t & 1;
        if (t + 1 < NT) {
            const int nxt = cur ^ 1;
            uint32_t sa = (uint32_t)__cvta_generic_to_shared(&Bs[nxt][tid * 2]);
            cp_async16(sa, &g_BfragH[(t + 1) * 512 + tid * 2]);
            asm volatile("cp.async.commit_group;" ::: "memory");
            asm volatile("cp.async.wait_group 1;" ::: "memory");
        } else {
            asm volatile("cp.async.wait_group 0;" ::: "memory");
        }
        __syncthreads();

        float Dh[2][4][4];
#pragma unroll
        for (int mf = 0; mf < 2; mf++)
#pragma unroll
            for (int nf = 0; nf < 4; nf++)
#pragma unroll
                for (int c = 0; c < 4; c++) Dh[mf][nf][c] = 0.f;

#pragma unroll
        for (int kc = 0; kc < 4; kc++) {
            uint2 bq[4];
#pragma unroll
            for (int nf = 0; nf < 4; nf++)
                bq[nf] = Bs[cur][(nf * 4 + kc) * 32 + lane];
#pragma unroll
            for (int mf = 0; mf < 2; mf++)
#pragma unroll
                for (int nf = 0; nf < 4; nf++)
                    mma_f16(Dh[mf][nf][0], Dh[mf][nf][1], Dh[mf][nf][2], Dh[mf][nf][3],
                            Ahi[mf][kc][0], Ahi[mf][kc][1], Ahi[mf][kc][2], Ahi[mf][kc][3],
                            bq[nf].x, bq[nf].y);
        }
        __syncthreads();

        const int nbase = t * 32;
#pragma unroll
        for (int nf = 0; nf < 4; nf++) {
            const int ncol = nbase + nf * 8 + (lane & 3) * 2;
            float2 en2 = *(const float2*)(g_enorm + ncol);
            TOP3(Dh[0][nf][0] - en2.x, ncol,     b0v00, b0i00, b1v00, b1i00, b2v00);
            TOP3(Dh[0][nf][1] - en2.y, ncol + 1, b0v00, b0i00, b1v00, b1i00, b2v00);
            TOP3(Dh[0][nf][2] - en2.x, ncol,     b0v01, b0i01, b1v01, b1i01, b2v01);
            TOP3(Dh[0][nf][3] - en2.y, ncol + 1, b0v01, b0i01, b1v01, b1i01, b2v01);
            TOP3(Dh[1][nf][0] - en2.x, ncol,     b0v10, b0i10, b1v10, b1i10, b2v10);
            TOP3(Dh[1][nf][1] - en2.y, ncol + 1, b0v10, b0i10, b1v10, b1i10, b2v10);
            TOP3(Dh[1][nf][2] - en2.x, ncol,     b0v11, b0i11, b1v11, b1i11, b2v11);
            TOP3(Dh[1][nf][3] - en2.y, ncol + 1, b0v11, b0i11, b1v11, b1i11, b2v11);
        }
    }

    // finalize each slot: quad max M, guard via quad-max of b2v, store top-2
#pragma unroll
    for (int s = 0; s < 4; s++) {
        float b0v = (s == 0) ? b0v00 : (s == 1) ? b0v01 : (s == 2) ? b0v10 : b0v11;
        float b1v = (s == 0) ? b1v00 : (s == 1) ? b1v01 : (s == 2) ? b1v10 : b1v11;
        float b2v = (s == 0) ? b2v00 : (s == 1) ? b2v01 : (s == 2) ? b2v10 : b2v11;
        int   b0i = (s == 0) ? b0i00 : (s == 1) ? b0i01 : (s == 2) ? b0i10 : b0i11;
        int   b1i = (s == 0) ? b1i00 : (s == 1) ? b1i01 : (s == 2) ? b1i10 : b1i11;
        int mf = s >> 1, rr = s & 1;
        float M = b0v;
        M = fmaxf(M, __shfl_xor_sync(0xffffffffu, M, 1));
        M = fmaxf(M, __shfl_xor_sync(0xffffffffu, M, 2));
        float G = b2v;
        G = fmaxf(G, __shfl_xor_sync(0xffffffffu, G, 1));
        G = fmaxf(G, __shfl_xor_sync(0xffffffffu, G, 2));
        int row = Wrow + mf * 16 + (lane >> 2) + rr * 8;
        int base = row * 8 + (lane & 3) * 2;
        g_cval[base] = b0v;     g_cidx[base] = b0i;
        g_cval[base + 1] = b1v; g_cidx[base + 1] = b1i;
        if ((lane & 3) == 0)
            g_rflag[row] = (G >= M - DELTA) ? 1 : 0;
    }
}

// ---------------------------------------------------------------------------
// Phase 2: exact evaluation. zsh holds 2*z (exact scale), so dot uses raw E.
// Candidate path: 8 cands, float4 E loads. Fallback: coalesced g_Et rescan.
// 1 warp per row; grid NPTS/8 x 256.
// ---------------------------------------------------------------------------
__global__ void __launch_bounds__(256) vq_verify(const float* __restrict__ z,
                                                 const float* __restrict__ E) {
    __shared__ float zsh[8][64];
    const int lane = threadIdx.x & 31;
    const int wid = threadIdx.x >> 5;
    const int row = blockIdx.x * 8 + wid;
    const int b = row >> 12;
    const int h = row & (HH - 1);
    const float* zrow = z + b * (CD * HH) + h;

    zsh[wid][lane]      = 2.0f * zrow[lane * HH];
    zsh[wid][lane + 32] = 2.0f * zrow[(lane + 32) * HH];
    __syncwarp();

    const float nzn = g_nzn[row];
    float bestv = -3.4e38f;
    int   besti = 0x7fffffff;

    if (!g_rflag[row]) {
        if (lane < 8) {
            int ix = g_cidx[row * 8 + lane];
            const float4* er4 = (const float4*)(E + ix * CD);
            float dot = 0.f;
#pragma unroll
            for (int q = 0; q < 16; q++) {
                float4 e4 = er4[q];
                dot = __fmaf_rn(zsh[wid][q * 4],     e4.x, dot);
                dot = __fmaf_rn(zsh[wid][q * 4 + 1], e4.y, dot);
                dot = __fmaf_rn(zsh[wid][q * 4 + 2], e4.z, dot);
                dot = __fmaf_rn(zsh[wid][q * 4 + 3], e4.w, dot);
            }
            bestv = __fadd_rn(__fadd_rn(nzn, -g_enorm[ix]), dot);
            besti = ix;
        }
    } else {
        // coalesced full rescan via transposed codebook (lanes adjacent in n)
        for (int n = lane; n < NCODE; n += 32) {
            float dot = 0.f;
#pragma unroll
            for (int k = 0; k < CD; k++)
                dot = __fmaf_rn(zsh[wid][k], g_Et[k * NCODE + n], dot);
            float d = __fadd_rn(__fadd_rn(nzn, -g_enorm[n]), dot);
            if (d > bestv) { bestv = d; besti = n; }
        }
    }

    // warp argmax with first-index tie-break
#pragma unroll
    for (int off = 16; off > 0; off >>= 1) {
        float ov = __shfl_xor_sync(0xffffffffu, bestv, off);
        int   oi = __shfl_xor_sync(0xffffffffu, besti, off);
        if (ov > bestv || (ov == bestv && oi < besti)) { bestv = ov; besti = oi; }
    }
    if (lane == 0) g_idx[row] = besti;
}

// ---------------------------------------------------------------------------
// Gather z_q (straight-through rounding emulated) + SSD partial.
// ---------------------------------------------------------------------------
__global__ void vq_gather(const float* __restrict__ z, const float* __restrict__ E,
                          float* __restrict__ out) {
    __shared__ float red[256];
    int tid = threadIdx.x;
    int base = (blockIdx.x * 256 + tid) * 4;
    int h = base & (HH - 1);
    int c = (base >> 12) & (CD - 1);
    int b = base >> 18;
    const int* gi = g_idx + b * HH + h;
    float4 zv = *(const float4*)(z + base);
    float e0 = E[gi[0] * CD + c];
    float e1 = E[gi[1] * CD + c];
    float e2 = E[gi[2] * CD + c];
    float e3 = E[gi[3] * CD + c];
    float d0 = __fadd_rn(e0, -zv.x);
    float d1 = __fadd_rn(e1, -zv.y);
    float d2 = __fadd_rn(e2, -zv.z);
    float d3 = __fadd_rn(e3, -zv.w);
    float4 o;
    o.x = __fadd_rn(zv.x, d0);
    o.y = __fadd_rn(zv.y, d1);
    o.z = __fadd_rn(zv.z, d2);
    o.w = __fadd_rn(zv.w, d3);
    *(float4*)(out + OUT_ZQ + base) = o;
    red[tid] = d0 * d0 + d1 * d1 + d2 * d2 + d3 * d3;
    __syncthreads();
    for (int off = 128; off > 0; off >>= 1) {
        if (tid < off) red[tid] += red[tid + off];
        __syncthreads();
    }
    if (tid == 0) g_partial[blockIdx.x] = red[0];
}

// ---------------------------------------------------------------------------
__global__ void vq_hist(float* __restrict__ out) {
    int n = blockIdx.x * 256 + threadIdx.x;
    int idx = g_idx[n];
    atomicAdd(&g_hist[idx], 1);
    out[OUT_IDX + n] = (float)idx;
}

// ---------------------------------------------------------------------------
__global__ void vq_final(float* __restrict__ out) {
    __shared__ float red[256];
    int tid = threadIdx.x;

    float s = 0.f;
    for (int i = tid; i < 2048; i += 256) s += g_partial[i];
    red[tid] = s;
    __syncthreads();
    for (int off = 128; off > 0; off >>= 1) {
        if (tid < off) red[tid] += red[tid + off];
        __syncthreads();
    }
    if (tid == 0)
        out[OUT_LOSS] = 1.25f * red[0] / (float)ZQ_ELEMS;
    __syncthreads();

    float ent = 0.f;
    for (int i = tid; i < NCODE; i += 256) {
        float p = (float)g_hist[i] * (1.f / (float)NPTS);
        ent += p * logf(p + 1e-10f);
    }
    red[tid] = ent;
    __syncthreads();
    for (int off = 128; off > 0; off >>= 1) {
        if (tid < off) red[tid] += red[tid + off];
        __syncthreads();
    }
    if (tid == 0) out[OUT_PERP] = expf(-red[0]);
}

// ---------------------------------------------------------------------------
extern "C" void kernel_launch(void* const* d_in, const int* in_sizes, int n_in,
                              void* d_out, int out_size) {
    const float* z = (const float*)d_in[0];        // (8, 64, 4096) f32
    const float* E = (const float*)d_in[1];        // (8192, 64) f32
    float* out = (float*)d_out;

    vq_prep      <<<2048, 256>>>(E);
    vq_prep_bfrag<<<512, 256>>>(E);
    vq_scan      <<<128, 256>>>(z);
    vq_verify    <<<NPTS / 8, 256>>>(z, E);
    vq_gather    <<<2048, 256>>>(z, E, out);
    vq_hist      <<<NPTS / 256, 256>>>(out);
    vq_final     <<<1, 256>>>(out);
}

// round 16
// speedup vs baseline: 9.4278x; 9.4278x over previous
#include <cuda_runtime.h>
#include <cuda_fp16.h>
#include <math.h>
#include <stdint.h>

// Problem constants
#define NB        8
#define CD        64
#define HH        4096
#define NPTS      (NB*HH)    // 32768
#define NCODE     8192
#define ZQ_ELEMS  (NB*CD*HH) // 2097152

// Output layout (flat float32): [z_q | loss | indices | perplexity]
#define OUT_ZQ    0
#define OUT_LOSS  ZQ_ELEMS
#define OUT_IDX   (ZQ_ELEMS + 1)
#define OUT_PERP  (ZQ_ELEMS + 1 + NPTS)

#define LO_SCALE   4096.0f
#define LO_INV     2.44140625e-4f   // 1/4096

// B fragments for mma.m16n8k16.f16: [nf(1024)][kc(4)][lane(32)] uint4 =
// (b0_hi, b1_hi, b0_lo, b1_lo); b0 = half2{B[k0][c],B[k0+1][c]}, b1 = k0+8 pair,
// c = nf*8 + lane/4, k0 = kc*16 + (lane%4)*2.  B[k][n] = 2*E[n][k], hi/lo fp16
// split with lo scaled by 4096.
__device__ uint4  g_Bfrag[1024 * 4 * 32];   // 2 MB
__device__ float  g_enorm[NCODE];
__device__ float  g_hval[NPTS * 2];         // per-half best value
__device__ int    g_hidx[NPTS * 2];         // per-half best index
__device__ int    g_idx[NPTS];
__device__ int    g_hist[NCODE];
__device__ float  g_partial[2048];

// ---------------------------------------------------------------------------
__device__ __forceinline__ uint32_t pack_h2(__half a, __half b) {
    __half2 h = __halves2half2(a, b);
    return *(uint32_t*)&h;
}

__device__ __forceinline__ void split16(float f, __half& hi, __half& lo) {
    hi = __float2half_rn(f);
    lo = __float2half_rn((f - __half2float(hi)) * LO_SCALE);
}

__device__ __forceinline__ void mma_f16(float& d0, float& d1, float& d2, float& d3,
                                        uint32_t a0, uint32_t a1, uint32_t a2, uint32_t a3,
                                        uint32_t b0, uint32_t b1) {
    asm volatile(
        "mma.sync.aligned.m16n8k16.row.col.f32.f16.f16.f32 "
        "{%0,%1,%2,%3},{%4,%5,%6,%7},{%8,%9},{%0,%1,%2,%3};"
        : "+f"(d0), "+f"(d1), "+f"(d2), "+f"(d3)
        : "r"(a0), "r"(a1), "r"(a2), "r"(a3), "r"(b0), "r"(b1));
}

__device__ __forceinline__ void cp_async16(uint32_t saddr, const void* gptr) {
    asm volatile("cp.async.cg.shared.global [%0], [%1], 16;" :: "r"(saddr), "l"(gptr));
}

// ---------------------------------------------------------------------------
// Prep A: |e|^2 (reference rounding chain) + zero histogram
// ---------------------------------------------------------------------------
__global__ void vq_prep(const float* __restrict__ E) {
    int idx = blockIdx.x * 256 + threadIdx.x;
    if (idx < NCODE) {
        const float* r = E + idx * CD;
        float s = 0.f;
#pragma unroll
        for (int d = 0; d < CD; d++) s = __fadd_rn(s, __fmul_rn(r[d], r[d]));
        g_enorm[idx] = s;
        g_hist[idx] = 0;
    }
}

// ---------------------------------------------------------------------------
// Prep B: pack codebook into m16n8k16 fragment-lane order, fp16 hi/lo of 2E.
// grid 512 x 256 -> 131072 threads, one uint4 each.
// ---------------------------------------------------------------------------
__global__ void vq_prep_bfrag(const float* __restrict__ E) {
    int idx = blockIdx.x * 256 + threadIdx.x;     // [nf*4+kc]*32 + lane
    int lane = idx & 31;
    int kc = (idx >> 5) & 3;
    int nf = idx >> 7;
    int n = nf * 8 + (lane >> 2);
    int k0 = kc * 16 + (lane & 3) * 2;
    const float* r = E + n * CD;
    float f0 = 2.0f * r[k0];
    float f1 = 2.0f * r[k0 + 1];
    float f2 = 2.0f * r[k0 + 8];
    float f3 = 2.0f * r[k0 + 9];
    __half h0, l0, h1, l1, h2, l2, h3, l3;
    split16(f0, h0, l0); split16(f1, h1, l1);
    split16(f2, h2, l2); split16(f3, h3, l3);
    uint4 v;
    v.x = pack_h2(h0, h1);   // b0 hi
    v.y = pack_h2(h2, h3);   // b1 hi
    v.z = pack_h2(l0, l1);   // b0 lo
    v.w = pack_h2(l2, l3);   // b1 lo
    g_Bfrag[idx] = v;
}

// ---------------------------------------------------------------------------
// Fused split-fp16 distance-GEMM + argmax over HALF the codebook per CTA.
// grid 256: CTA = (m-tile = blk>>1) x (codebook half = blk&1).
// Within-half logic identical to the proven R6 kernel.
// ---------------------------------------------------------------------------
__global__ void __launch_bounds__(256, 1) vq_argmax(const float* __restrict__ z) {
    __shared__ uint4 Bs[2][512];     // 16 KB double buffer (n-tile of 32 codes)

    const int tid = threadIdx.x;
    const int lane = tid & 31;
    const int w = tid >> 5;
    const int blk = blockIdx.x;
    const int mtile = blk >> 1;
    const int half = blk & 1;
    const int b = (mtile * 256) >> 12;
    const int hb = (mtile * 256) & (HH - 1);
    const float* zb = z + b * (CD * HH);
    const int hw = hb + w * 32;

    // ---- -|z|^2 per row (reference sequential chain); lane l -> row hw+l
    float s = 0.f;
    {
        int h = hw + lane;
#pragma unroll
        for (int k = 0; k < CD; k++) {
            float v = zb[k * HH + h];
            s = __fadd_rn(s, __fmul_rn(v, v));
        }
    }
    float nznl = -s;
    float nzn[2][2];
#pragma unroll
    for (int mf = 0; mf < 2; mf++) {
        nzn[mf][0] = __shfl_sync(0xffffffffu, nznl, mf * 16 + (lane >> 2));
        nzn[mf][1] = __shfl_sync(0xffffffffu, nznl, mf * 16 + (lane >> 2) + 8);
    }

    // ---- A fragments (hi/lo fp16), resident for whole half-N sweep
    uint32_t Ahi[2][4][4], Alo[2][4][4];
#pragma unroll
    for (int mf = 0; mf < 2; mf++) {
        int r0 = hw + mf * 16 + (lane >> 2);
        int r1 = r0 + 8;
#pragma unroll
        for (int kc = 0; kc < 4; kc++) {
            int k0 = kc * 16 + (lane & 3) * 2;
#pragma unroll
            for (int q = 0; q < 4; q++) {
                int rr = (q & 1) ? r1 : r0;
                int kk = k0 + ((q & 2) ? 8 : 0);
                float fA = zb[kk * HH + rr];
                float fB = zb[(kk + 1) * HH + rr];
                __half hA, lA, hB, lB;
                split16(fA, hA, lA);
                split16(fB, hB, lB);
                Ahi[mf][kc][q] = pack_h2(hA, hB);
                Alo[mf][kc][q] = pack_h2(lA, lB);
            }
        }
    }

    float best[2][2];
    int   bidx[2][2];
#pragma unroll
    for (int mf = 0; mf < 2; mf++)
#pragma unroll
        for (int rr = 0; rr < 2; rr++) { best[mf][rr] = -3.4e38f; bidx[mf][rr] = 0; }

    const int T0 = half * 128;       // first n-tile of this half
    const int NT = 128;              // tiles per half (32 codes each)

    // prologue: stage tile T0 into buf 0 (512 uint4, 2 per thread)
    {
#pragma unroll
        for (int i = 0; i < 2; i++) {
            int q = tid + i * 256;
            uint32_t sa = (uint32_t)__cvta_generic_to_shared(&Bs[0][q]);
            cp_async16(sa, &g_Bfrag[T0 * 512 + q]);
        }
        asm volatile("cp.async.commit_group;" ::: "memory");
    }

#pragma unroll 1
    for (int tt = 0; tt < NT; tt++) {
        const int t = T0 + tt;
        const int cur = tt & 1;
        if (tt + 1 < NT) {
            const int nxt = cur ^ 1;
#pragma unroll
            for (int i = 0; i < 2; i++) {
                int q = tid + i * 256;
                uint32_t sa = (uint32_t)__cvta_generic_to_shared(&Bs[nxt][q]);
                cp_async16(sa, &g_Bfrag[(t + 1) * 512 + q]);
            }
            asm volatile("cp.async.commit_group;" ::: "memory");
            asm volatile("cp.async.wait_group 1;" ::: "memory");
        } else {
            asm volatile("cp.async.wait_group 0;" ::: "memory");
        }
        __syncthreads();   // tile t visible

        float Dh[2][4][4], Dx[2][4][4];
#pragma unroll
        for (int mf = 0; mf < 2; mf++)
#pragma unroll
            for (int nf = 0; nf < 4; nf++)
#pragma unroll
                for (int c = 0; c < 4; c++) { Dh[mf][nf][c] = 0.f; Dx[mf][nf][c] = 0.f; }

#pragma unroll
        for (int kc = 0; kc < 4; kc++) {
            uint4 bq[4];
#pragma unroll
            for (int nf = 0; nf < 4; nf++)
                bq[nf] = Bs[cur][(nf * 4 + kc) * 32 + lane];
#pragma unroll
            for (int mf = 0; mf < 2; mf++)
#pragma unroll
                for (int nf = 0; nf < 4; nf++) {
                    // hi*hi -> Dh
                    mma_f16(Dh[mf][nf][0], Dh[mf][nf][1], Dh[mf][nf][2], Dh[mf][nf][3],
                            Ahi[mf][kc][0], Ahi[mf][kc][1], Ahi[mf][kc][2], Ahi[mf][kc][3],
                            bq[nf].x, bq[nf].y);
                    // hi*lo + lo*hi -> Dx (scale 4096)
                    mma_f16(Dx[mf][nf][0], Dx[mf][nf][1], Dx[mf][nf][2], Dx[mf][nf][3],
                            Ahi[mf][kc][0], Ahi[mf][kc][1], Ahi[mf][kc][2], Ahi[mf][kc][3],
                            bq[nf].z, bq[nf].w);
                    mma_f16(Dx[mf][nf][0], Dx[mf][nf][1], Dx[mf][nf][2], Dx[mf][nf][3],
                            Alo[mf][kc][0], Alo[mf][kc][1], Alo[mf][kc][2], Alo[mf][kc][3],
                            bq[nf].x, bq[nf].y);
                }
        }
        __syncthreads();   // reads of buf `cur` done before tt+1 overwrites

        // epilogue: dot = Dh + Dx/4096; v = fl(fl(-zn - en) + dot)
        const int nbase = t * 32;
#pragma unroll
        for (int nf = 0; nf < 4; nf++) {
            const int ncol = nbase + nf * 8 + (lane & 3) * 2;
            float2 en2 = *(const float2*)(g_enorm + ncol);
#pragma unroll
            for (int mf = 0; mf < 2; mf++) {
                float dot0 = __fmaf_rn(Dx[mf][nf][0], LO_INV, Dh[mf][nf][0]);
                float dot1 = __fmaf_rn(Dx[mf][nf][1], LO_INV, Dh[mf][nf][1]);
                float dot2 = __fmaf_rn(Dx[mf][nf][2], LO_INV, Dh[mf][nf][2]);
                float dot3 = __fmaf_rn(Dx[mf][nf][3], LO_INV, Dh[mf][nf][3]);
                float v0 = __fadd_rn(__fadd_rn(nzn[mf][0], -en2.x), dot0);
                if (v0 > best[mf][0]) { best[mf][0] = v0; bidx[mf][0] = ncol; }
                float v1 = __fadd_rn(__fadd_rn(nzn[mf][0], -en2.y), dot1);
                if (v1 > best[mf][0]) { best[mf][0] = v1; bidx[mf][0] = ncol + 1; }
                float v2 = __fadd_rn(__fadd_rn(nzn[mf][1], -en2.x), dot2);
                if (v2 > best[mf][1]) { best[mf][1] = v2; bidx[mf][1] = ncol; }
                float v3 = __fadd_rn(__fadd_rn(nzn[mf][1], -en2.y), dot3);
                if (v3 > best[mf][1]) { best[mf][1] = v3; bidx[mf][1] = ncol + 1; }
            }
        }
    }

    // quad reduce (lanes sharing a row differ in lane%4), first-index tie-break
    const int Wrow = mtile * 256 + w * 32;
#pragma unroll
    for (int mf = 0; mf < 2; mf++)
#pragma unroll
        for (int rr = 0; rr < 2; rr++) {
            float v = best[mf][rr];
            int ix = bidx[mf][rr];
#pragma unroll
            for (int off = 1; off <= 2; off <<= 1) {
                float ov = __shfl_xor_sync(0xffffffffu, v, off);
                int   oi = __shfl_xor_sync(0xffffffffu, ix, off);
                if (ov > v || (ov == v && oi < ix)) { v = ov; ix = oi; }
            }
            if ((lane & 3) == 0) {
                int row = Wrow + mf * 16 + (lane >> 2) + rr * 8;
                g_hval[row * 2 + half] = v;
                g_hidx[row * 2 + half] = ix;
            }
        }
}

// ---------------------------------------------------------------------------
// Combine halves: half-0 indices < half-1 indices, so prefer half 0 on ties.
// grid 128 x 256.
// ---------------------------------------------------------------------------
__global__ void vq_combine(void) {
    int n = blockIdx.x * 256 + threadIdx.x;
    float v0 = g_hval[n * 2];
    float v1 = g_hval[n * 2 + 1];
    g_idx[n] = (v1 > v0) ? g_hidx[n * 2 + 1] : g_hidx[n * 2];
}

// ---------------------------------------------------------------------------
// Gather z_q (straight-through rounding emulated, bit-exact) + SSD partial.
// ---------------------------------------------------------------------------
__global__ void vq_gather(const float* __restrict__ z, const float* __restrict__ E,
                          float* __restrict__ out) {
    __shared__ float red[256];
    int tid = threadIdx.x;
    int base = (blockIdx.x * 256 + tid) * 4;
    int h = base & (HH - 1);
    int c = (base >> 12) & (CD - 1);
    int b = base >> 18;
    const int* gi = g_idx + b * HH + h;
    float4 zv = *(const float4*)(z + base);
    float e0 = E[gi[0] * CD + c];
    float e1 = E[gi[1] * CD + c];
    float e2 = E[gi[2] * CD + c];
    float e3 = E[gi[3] * CD + c];
    float d0 = __fadd_rn(e0, -zv.x);
    float d1 = __fadd_rn(e1, -zv.y);
    float d2 = __fadd_rn(e2, -zv.z);
    float d3 = __fadd_rn(e3, -zv.w);
    // straight-through: out = fl(z + fl(e - z))
    float4 o;
    o.x = __fadd_rn(zv.x, d0);
    o.y = __fadd_rn(zv.y, d1);
    o.z = __fadd_rn(zv.z, d2);
    o.w = __fadd_rn(zv.w, d3);
    *(float4*)(out + OUT_ZQ + base) = o;
    red[tid] = d0 * d0 + d1 * d1 + d2 * d2 + d3 * d3;
    __syncthreads();
    for (int off = 128; off > 0; off >>= 1) {
        if (tid < off) red[tid] += red[tid + off];
        __syncthreads();
    }
    if (tid == 0) g_partial[blockIdx.x] = red[0];
}

// ---------------------------------------------------------------------------
__global__ void vq_hist(float* __restrict__ out) {
    int n = blockIdx.x * 256 + threadIdx.x;
    int idx = g_idx[n];
    atomicAdd(&g_hist[idx], 1);
    out[OUT_IDX + n] = (float)idx;
}

// ---------------------------------------------------------------------------
__global__ void vq_final(float* __restrict__ out) {
    __shared__ float red[256];
    int tid = threadIdx.x;

    float s = 0.f;
    for (int i = tid; i < 2048; i += 256) s += g_partial[i];
    red[tid] = s;
    __syncthreads();
    for (int off = 128; off > 0; off >>= 1) {
        if (tid < off) red[tid] += red[tid + off];
        __syncthreads();
    }
    if (tid == 0)
        out[OUT_LOSS] = 1.25f * red[0] / (float)ZQ_ELEMS;
    __syncthreads();

    float ent = 0.f;
    for (int i = tid; i < NCODE; i += 256) {
        float p = (float)g_hist[i] * (1.f / (float)NPTS);
        ent += p * logf(p + 1e-10f);
    }
    red[tid] = ent;
    __syncthreads();
    for (int off = 128; off > 0; off >>= 1) {
        if (tid < off) red[tid] += red[tid + off];
        __syncthreads();
    }
    if (tid == 0) out[OUT_PERP] = expf(-red[0]);
}

// ---------------------------------------------------------------------------
extern "C" void kernel_launch(void* const* d_in, const int* in_sizes, int n_in,
                              void* d_out, int out_size) {
    const float* z = (const float*)d_in[0];        // (8, 64, 4096) f32
    const float* E = (const float*)d_in[1];        // (8192, 64) f32
    float* out = (float*)d_out;

    vq_prep      <<<32, 256>>>(E);
    vq_prep_bfrag<<<512, 256>>>(E);
    vq_argmax    <<<256, 256>>>(z);
    vq_combine   <<<128, 256>>>();
    vq_gather    <<<2048, 256>>>(z, E, out);
    vq_hist      <<<NPTS / 256, 256>>>(out);
    vq_final     <<<1, 256>>>(out);
}

// round 17
// speedup vs baseline: 10.1263x; 1.0741x over previous
#include <cuda_runtime.h>
#include <cuda_fp16.h>
#include <math.h>
#include <stdint.h>

// Problem constants
#define NB        8
#define CD        64
#define HH        4096
#define NPTS      (NB*HH)    // 32768
#define NCODE     8192
#define ZQ_ELEMS  (NB*CD*HH) // 2097152

// Output layout (flat float32): [z_q | loss | indices | perplexity]
#define OUT_ZQ    0
#define OUT_LOSS  ZQ_ELEMS
#define OUT_IDX   (ZQ_ELEMS + 1)
#define OUT_PERP  (ZQ_ELEMS + 1 + NPTS)

#define LO_SCALE   4096.0f
#define LO_INV     2.44140625e-4f   // 1/4096

#define NCHUNK    8          // codebook chunks (1024 codes = 32 n-tiles each)
#define NITEMS    (128 * NCHUNK)

// B fragments for mma.m16n8k16.f16: [nf(1024)][kc(4)][lane(32)] uint4 =
// (b0_hi, b1_hi, b0_lo, b1_lo). B[k][n] = 2*E[n][k], fp16 hi/lo, lo scaled 4096.
__device__ uint4  g_Bfrag[1024 * 4 * 32];   // 2 MB
__device__ float  g_enorm[NCODE];
__device__ float  g_pval[NPTS * NCHUNK];    // per-(row,chunk) best value
__device__ int    g_pidx[NPTS * NCHUNK];    // per-(row,chunk) best index
__device__ int    g_idx[NPTS];
__device__ int    g_hist[NCODE];
__device__ float  g_partial[2048];
__device__ int    g_work;                   // persistent work counter

// ---------------------------------------------------------------------------
__device__ __forceinline__ uint32_t pack_h2(__half a, __half b) {
    __half2 h = __halves2half2(a, b);
    return *(uint32_t*)&h;
}

__device__ __forceinline__ void split16(float f, __half& hi, __half& lo) {
    hi = __float2half_rn(f);
    lo = __float2half_rn((f - __half2float(hi)) * LO_SCALE);
}

__device__ __forceinline__ void mma_f16(float& d0, float& d1, float& d2, float& d3,
                                        uint32_t a0, uint32_t a1, uint32_t a2, uint32_t a3,
                                        uint32_t b0, uint32_t b1) {
    asm volatile(
        "mma.sync.aligned.m16n8k16.row.col.f32.f16.f16.f32 "
        "{%0,%1,%2,%3},{%4,%5,%6,%7},{%8,%9},{%0,%1,%2,%3};"
        : "+f"(d0), "+f"(d1), "+f"(d2), "+f"(d3)
        : "r"(a0), "r"(a1), "r"(a2), "r"(a3), "r"(b0), "r"(b1));
}

__device__ __forceinline__ void cp_async16(uint32_t saddr, const void* gptr) {
    asm volatile("cp.async.cg.shared.global [%0], [%1], 16;" :: "r"(saddr), "l"(gptr));
}

// ---------------------------------------------------------------------------
// Prep A: |e|^2 (reference rounding chain) + zero histogram + reset counter
// ---------------------------------------------------------------------------
__global__ void vq_prep(const float* __restrict__ E) {
    int idx = blockIdx.x * 256 + threadIdx.x;
    if (idx == 0) g_work = 0;
    if (idx < NCODE) {
        const float* r = E + idx * CD;
        float s = 0.f;
#pragma unroll
        for (int d = 0; d < CD; d++) s = __fadd_rn(s, __fmul_rn(r[d], r[d]));
        g_enorm[idx] = s;
        g_hist[idx] = 0;
    }
}

// ---------------------------------------------------------------------------
// Prep B: pack codebook into m16n8k16 fragment-lane order, fp16 hi/lo of 2E.
// ---------------------------------------------------------------------------
__global__ void vq_prep_bfrag(const float* __restrict__ E) {
    int idx = blockIdx.x * 256 + threadIdx.x;     // [nf*4+kc]*32 + lane
    int lane = idx & 31;
    int kc = (idx >> 5) & 3;
    int nf = idx >> 7;
    int n = nf * 8 + (lane >> 2);
    int k0 = kc * 16 + (lane & 3) * 2;
    const float* r = E + n * CD;
    float f0 = 2.0f * r[k0];
    float f1 = 2.0f * r[k0 + 1];
    float f2 = 2.0f * r[k0 + 8];
    float f3 = 2.0f * r[k0 + 9];
    __half h0, l0, h1, l1, h2, l2, h3, l3;
    split16(f0, h0, l0); split16(f1, h1, l1);
    split16(f2, h2, l2); split16(f3, h3, l3);
    uint4 v;
    v.x = pack_h2(h0, h1);
    v.y = pack_h2(h2, h3);
    v.z = pack_h2(l0, l1);
    v.w = pack_h2(l2, l3);
    g_Bfrag[idx] = v;
}

// ---------------------------------------------------------------------------
// Persistent fused split-fp16 distance-GEMM + argmax.
// grid 148 (one CTA/SM). Work item = (mtile 0..127, chunk 0..7);
// chunk covers 32 n-tiles (1024 codes). Inner loop identical to proven R6.
// ---------------------------------------------------------------------------
__global__ void __launch_bounds__(256, 1) vq_argmax(const float* __restrict__ z) {
    __shared__ uint4 Bs[2][512];     // 16 KB double buffer (n-tile of 32 codes)
    __shared__ int s_item;

    const int tid = threadIdx.x;
    const int lane = tid & 31;
    const int w = tid >> 5;

    for (;;) {
        __syncthreads();             // protect s_item and Bs reuse across items
        if (tid == 0) s_item = atomicAdd(&g_work, 1);
        __syncthreads();
        const int item = s_item;
        if (item >= NITEMS) break;
        const int mtile = item >> 3;
        const int chunk = item & 7;

        const int b = (mtile * 256) >> 12;
        const int hb = (mtile * 256) & (HH - 1);
        const float* zb = z + b * (CD * HH);
        const int hw = hb + w * 32;

        // ---- -|z|^2 per row (reference sequential chain); lane l -> row hw+l
        float s = 0.f;
        {
            int h = hw + lane;
#pragma unroll
            for (int k = 0; k < CD; k++) {
                float v = zb[k * HH + h];
                s = __fadd_rn(s, __fmul_rn(v, v));
            }
        }
        float nznl = -s;
        float nzn[2][2];
#pragma unroll
        for (int mf = 0; mf < 2; mf++) {
            nzn[mf][0] = __shfl_sync(0xffffffffu, nznl, mf * 16 + (lane >> 2));
            nzn[mf][1] = __shfl_sync(0xffffffffu, nznl, mf * 16 + (lane >> 2) + 8);
        }

        // ---- A fragments (hi/lo fp16), resident for this item's N sweep
        uint32_t Ahi[2][4][4], Alo[2][4][4];
#pragma unroll
        for (int mf = 0; mf < 2; mf++) {
            int r0 = hw + mf * 16 + (lane >> 2);
            int r1 = r0 + 8;
#pragma unroll
            for (int kc = 0; kc < 4; kc++) {
                int k0 = kc * 16 + (lane & 3) * 2;
#pragma unroll
                for (int q = 0; q < 4; q++) {
                    int rr = (q & 1) ? r1 : r0;
                    int kk = k0 + ((q & 2) ? 8 : 0);
                    float fA = zb[kk * HH + rr];
                    float fB = zb[(kk + 1) * HH + rr];
                    __half hA, lA, hB, lB;
                    split16(fA, hA, lA);
                    split16(fB, hB, lB);
                    Ahi[mf][kc][q] = pack_h2(hA, hB);
                    Alo[mf][kc][q] = pack_h2(lA, lB);
                }
            }
        }

        float best[2][2];
        int   bidx[2][2];
#pragma unroll
        for (int mf = 0; mf < 2; mf++)
#pragma unroll
            for (int rr = 0; rr < 2; rr++) { best[mf][rr] = -3.4e38f; bidx[mf][rr] = 0; }

        const int T0 = chunk * 32;   // first n-tile of this chunk
        const int NT = 32;           // n-tiles per chunk

        // prologue: stage tile T0 into buf 0
        {
#pragma unroll
            for (int i = 0; i < 2; i++) {
                int q = tid + i * 256;
                uint32_t sa = (uint32_t)__cvta_generic_to_shared(&Bs[0][q]);
                cp_async16(sa, &g_Bfrag[T0 * 512 + q]);
            }
            asm volatile("cp.async.commit_group;" ::: "memory");
        }

#pragma unroll 1
        for (int tt = 0; tt < NT; tt++) {
            const int t = T0 + tt;
            const int cur = tt & 1;
            if (tt + 1 < NT) {
                const int nxt = cur ^ 1;
#pragma unroll
                for (int i = 0; i < 2; i++) {
                    int q = tid + i * 256;
                    uint32_t sa = (uint32_t)__cvta_generic_to_shared(&Bs[nxt][q]);
                    cp_async16(sa, &g_Bfrag[(t + 1) * 512 + q]);
                }
                asm volatile("cp.async.commit_group;" ::: "memory");
                asm volatile("cp.async.wait_group 1;" ::: "memory");
            } else {
                asm volatile("cp.async.wait_group 0;" ::: "memory");
            }
            __syncthreads();   // tile t visible

            float Dh[2][4][4], Dx[2][4][4];
#pragma unroll
            for (int mf = 0; mf < 2; mf++)
#pragma unroll
                for (int nf = 0; nf < 4; nf++)
#pragma unroll
                    for (int c = 0; c < 4; c++) { Dh[mf][nf][c] = 0.f; Dx[mf][nf][c] = 0.f; }

#pragma unroll
            for (int kc = 0; kc < 4; kc++) {
                uint4 bq[4];
#pragma unroll
                for (int nf = 0; nf < 4; nf++)
                    bq[nf] = Bs[cur][(nf * 4 + kc) * 32 + lane];
#pragma unroll
                for (int mf = 0; mf < 2; mf++)
#pragma unroll
                    for (int nf = 0; nf < 4; nf++) {
                        mma_f16(Dh[mf][nf][0], Dh[mf][nf][1], Dh[mf][nf][2], Dh[mf][nf][3],
                                Ahi[mf][kc][0], Ahi[mf][kc][1], Ahi[mf][kc][2], Ahi[mf][kc][3],
                                bq[nf].x, bq[nf].y);
                        mma_f16(Dx[mf][nf][0], Dx[mf][nf][1], Dx[mf][nf][2], Dx[mf][nf][3],
                                Ahi[mf][kc][0], Ahi[mf][kc][1], Ahi[mf][kc][2], Ahi[mf][kc][3],
                                bq[nf].z, bq[nf].w);
                        mma_f16(Dx[mf][nf][0], Dx[mf][nf][1], Dx[mf][nf][2], Dx[mf][nf][3],
                                Alo[mf][kc][0], Alo[mf][kc][1], Alo[mf][kc][2], Alo[mf][kc][3],
                                bq[nf].x, bq[nf].y);
                    }
            }
            __syncthreads();   // reads of buf `cur` done before tt+1 overwrites

            // epilogue: dot = Dh + Dx/4096; v = fl(fl(-zn - en) + dot)
            const int nbase = t * 32;
#pragma unroll
            for (int nf = 0; nf < 4; nf++) {
                const int ncol = nbase + nf * 8 + (lane & 3) * 2;
                float2 en2 = *(const float2*)(g_enorm + ncol);
#pragma unroll
                for (int mf = 0; mf < 2; mf++) {
                    float dot0 = __fmaf_rn(Dx[mf][nf][0], LO_INV, Dh[mf][nf][0]);
                    float dot1 = __fmaf_rn(Dx[mf][nf][1], LO_INV, Dh[mf][nf][1]);
                    float dot2 = __fmaf_rn(Dx[mf][nf][2], LO_INV, Dh[mf][nf][2]);
                    float dot3 = __fmaf_rn(Dx[mf][nf][3], LO_INV, Dh[mf][nf][3]);
                    float v0 = __fadd_rn(__fadd_rn(nzn[mf][0], -en2.x), dot0);
                    if (v0 > best[mf][0]) { best[mf][0] = v0; bidx[mf][0] = ncol; }
                    float v1 = __fadd_rn(__fadd_rn(nzn[mf][0], -en2.y), dot1);
                    if (v1 > best[mf][0]) { best[mf][0] = v1; bidx[mf][0] = ncol + 1; }
                    float v2 = __fadd_rn(__fadd_rn(nzn[mf][1], -en2.x), dot2);
                    if (v2 > best[mf][1]) { best[mf][1] = v2; bidx[mf][1] = ncol; }
                    float v3 = __fadd_rn(__fadd_rn(nzn[mf][1], -en2.y), dot3);
                    if (v3 > best[mf][1]) { best[mf][1] = v3; bidx[mf][1] = ncol + 1; }
                }
            }
        }

        // quad reduce (lanes sharing a row differ in lane%4), first-index tie-break
        const int Wrow = mtile * 256 + w * 32;
#pragma unroll
        for (int mf = 0; mf < 2; mf++)
#pragma unroll
            for (int rr = 0; rr < 2; rr++) {
                float v = best[mf][rr];
                int ix = bidx[mf][rr];
#pragma unroll
                for (int off = 1; off <= 2; off <<= 1) {
                    float ov = __shfl_xor_sync(0xffffffffu, v, off);
                    int   oi = __shfl_xor_sync(0xffffffffu, ix, off);
                    if (ov > v || (ov == v && oi < ix)) { v = ov; ix = oi; }
                }
                if ((lane & 3) == 0) {
                    int row = Wrow + mf * 16 + (lane >> 2) + rr * 8;
                    g_pval[row * NCHUNK + chunk] = v;
                    g_pidx[row * NCHUNK + chunk] = ix;
                }
            }
    }
}

// ---------------------------------------------------------------------------
// Merge chunks (ascending chunk = ascending index; strict > keeps first),
// histogram, and write indices as float. grid 128 x 256.
// ---------------------------------------------------------------------------
__global__ void vq_hist(float* __restrict__ out) {
    int n = blockIdx.x * 256 + threadIdx.x;
    float bv = g_pval[n * NCHUNK];
    int bi = g_pidx[n * NCHUNK];
#pragma unroll
    for (int c = 1; c < NCHUNK; c++) {
        float v = g_pval[n * NCHUNK + c];
        if (v > bv) { bv = v; bi = g_pidx[n * NCHUNK + c]; }
    }
    g_idx[n] = bi;
    atomicAdd(&g_hist[bi], 1);
    out[OUT_IDX + n] = (float)bi;
}

// ---------------------------------------------------------------------------
// Gather z_q (straight-through rounding emulated, bit-exact) + SSD partial.
// ---------------------------------------------------------------------------
__global__ void vq_gather(const float* __restrict__ z, const float* __restrict__ E,
                          float* __restrict__ out) {
    __shared__ float red[256];
    int tid = threadIdx.x;
    int base = (blockIdx.x * 256 + tid) * 4;
    int h = base & (HH - 1);
    int c = (base >> 12) & (CD - 1);
    int b = base >> 18;
    const int* gi = g_idx + b * HH + h;
    float4 zv = *(const float4*)(z + base);
    float e0 = E[gi[0] * CD + c];
    float e1 = E[gi[1] * CD + c];
    float e2 = E[gi[2] * CD + c];
    float e3 = E[gi[3] * CD + c];
    float d0 = __fadd_rn(e0, -zv.x);
    float d1 = __fadd_rn(e1, -zv.y);
    float d2 = __fadd_rn(e2, -zv.z);
    float d3 = __fadd_rn(e3, -zv.w);
    // straight-through: out = fl(z + fl(e - z))
    float4 o;
    o.x = __fadd_rn(zv.x, d0);
    o.y = __fadd_rn(zv.y, d1);
    o.z = __fadd_rn(zv.z, d2);
    o.w = __fadd_rn(zv.w, d3);
    *(float4*)(out + OUT_ZQ + base) = o;
    red[tid] = d0 * d0 + d1 * d1 + d2 * d2 + d3 * d3;
    __syncthreads();
    for (int off = 128; off > 0; off >>= 1) {
        if (tid < off) red[tid] += red[tid + off];
        __syncthreads();
    }
    if (tid == 0) g_partial[blockIdx.x] = red[0];
}

// ---------------------------------------------------------------------------
__global__ void vq_final(float* __restrict__ out) {
    __shared__ float red[256];
    int tid = threadIdx.x;

    float s = 0.f;
    for (int i = tid; i < 2048; i += 256) s += g_partial[i];
    red[tid] = s;
    __syncthreads();
    for (int off = 128; off > 0; off >>= 1) {
        if (tid < off) red[tid] += red[tid + off];
        __syncthreads();
    }
    if (tid == 0)
        out[OUT_LOSS] = 1.25f * red[0] / (float)ZQ_ELEMS;
    __syncthreads();

    float ent = 0.f;
    for (int i = tid; i < NCODE; i += 256) {
        float p = (float)g_hist[i] * (1.f / (float)NPTS);
        ent += p * logf(p + 1e-10f);
    }
    red[tid] = ent;
    __syncthreads();
    for (int off = 128; off > 0; off >>= 1) {
        if (tid < off) red[tid] += red[tid + off];
        __syncthreads();
    }
    if (tid == 0) out[OUT_PERP] = expf(-red[0]);
}

// ---------------------------------------------------------------------------
extern "C" void kernel_launch(void* const* d_in, const int* in_sizes, int n_in,
                              void* d_out, int out_size) {
    const float* z = (const float*)d_in[0];        // (8, 64, 4096) f32
    const float* E = (const float*)d_in[1];        // (8192, 64) f32
    float* out = (float*)d_out;

    vq_prep      <<<32, 256>>>(E);
    vq_prep_bfrag<<<512, 256>>>(E);
    vq_argmax    <<<148, 256>>>(z);
    vq_hist      <<<NPTS / 256, 256>>>(out);
    vq_gather    <<<2048, 256>>>(z, E, out);
    vq_final     <<<1, 256>>>(out);
}